// round 1
// baseline (speedup 1.0000x reference)
#include <cuda_runtime.h>
#include <cuda_bf16.h>

typedef unsigned long long ull;

#define GMM_M   64
#define GMM_D   16
#define GMM_KP  8      // 16 dims = 8 f32x2 pairs
#define TPB     128    // threads per block (main kernel)
#define PPT     2      // points per thread
#define PPB     (TPB*PPT)

// Precomputed per-mixture params, packed as f32x2 pairs.
__device__ ull   g_A[GMM_M * GMM_KP];   // -0.5 * prec, pairs
__device__ ull   g_B[GMM_M * GMM_KP];   //  prec * mu,  pairs
__device__ float g_C[GMM_M];            //  log(w * (2pi)^-8 * |S|^-1/2) - 0.5*sum(prec*mu^2)
__device__ float g_part[8192];          //  per-block partial log-like sums

// ---------- packed f32x2 helpers (FFMA2 not emitted by ptxas from C++) ----------
__device__ __forceinline__ ull pk2(float lo, float hi) {
    ull r; asm("mov.b64 %0, {%1, %2};" : "=l"(r) : "f"(lo), "f"(hi)); return r;
}
__device__ __forceinline__ void upk2(ull v, float &lo, float &hi) {
    asm("mov.b64 {%0, %1}, %2;" : "=f"(lo), "=f"(hi) : "l"(v));
}
__device__ __forceinline__ ull fma2(ull a, ull b, ull c) {
    ull r; asm("fma.rn.f32x2 %0, %1, %2, %3;" : "=l"(r) : "l"(a), "l"(b), "l"(c)); return r;
}
__device__ __forceinline__ ull mul2(ull a, ull b) {
    ull r; asm("mul.rn.f32x2 %0, %1, %2;" : "=l"(r) : "l"(a), "l"(b)); return r;
}

// ---------- kernel 1: per-mixture parameter precompute (tiny) ----------
__global__ void gmm_precompute(const float* __restrict__ wghts,
                               const float* __restrict__ means,
                               const float* __restrict__ dcovs) {
    int m = threadIdx.x;
    if (m >= GMM_M) return;
    float A[GMM_D], B[GMM_D];
    // log( w * (2pi)^{-D/2} ) ; PI2 matches reference constant
    float csum = logf(wghts[m]) - 8.0f * logf(6.283185307f);
    #pragma unroll
    for (int d = 0; d < GMM_D; d++) {
        float dc   = dcovs[m * GMM_D + d];
        float mu   = means[m * GMM_D + d];
        float prec = 1.0f / dc;
        A[d] = -0.5f * prec;
        B[d] = prec * mu;
        csum += -0.5f * prec * mu * mu - 0.5f * logf(dc);
    }
    #pragma unroll
    for (int k = 0; k < GMM_KP; k++) {
        g_A[m * GMM_KP + k] = pk2(A[2 * k], A[2 * k + 1]);
        g_B[m * GMM_KP + k] = pk2(B[2 * k], B[2 * k + 1]);
    }
    g_C[m] = csum;
}

// ---------- kernel 2: main GMM E-step ----------
__global__ void __launch_bounds__(TPB)
gmm_main(const float* __restrict__ data,
         const float* __restrict__ means,
         float* __restrict__ out,   // out[0]=loglike (written by finalize), out[1..]=e_means
         int T) {
    __shared__ ull   sA[GMM_M * GMM_KP];
    __shared__ ull   sB[GMM_M * GMM_KP];
    __shared__ ull   sMu[GMM_M * GMM_KP];
    __shared__ float sC[GMM_M];
    __shared__ float sRed[TPB];

    const int tid = threadIdx.x;
    const ull* gmu = (const ull*)means;   // means rows are contiguous f32 pairs
    for (int i = tid; i < GMM_M * GMM_KP; i += TPB) {
        sA[i]  = g_A[i];
        sB[i]  = g_B[i];
        sMu[i] = gmu[i];
    }
    if (tid < GMM_M) sC[tid] = g_C[tid];
    __syncthreads();

    const int base = blockIdx.x * PPB;
    int  t[PPT];
    bool v[PPT];
    #pragma unroll
    for (int j = 0; j < PPT; j++) { t[j] = base + tid + j * TPB; v[j] = (t[j] < T); }

    ull  x[PPT][GMM_KP], xx[PPT][GMM_KP], num[PPT][GMM_KP];
    float like[PPT];

    #pragma unroll
    for (int j = 0; j < PPT; j++) {
        like[j] = 0.0f;
        if (v[j]) {
            const ull* dp = (const ull*)(data + (size_t)t[j] * GMM_D);
            #pragma unroll
            for (int k = 0; k < GMM_KP; k++) {
                x[j][k]  = dp[k];
                xx[j][k] = mul2(x[j][k], x[j][k]);
            }
        } else {
            #pragma unroll
            for (int k = 0; k < GMM_KP; k++) { x[j][k] = 0ULL; xx[j][k] = 0ULL; }
        }
        #pragma unroll
        for (int k = 0; k < GMM_KP; k++) num[j][k] = 0ULL;
    }

    #pragma unroll 2
    for (int m = 0; m < GMM_M; m++) {
        ull accA[PPT], accB[PPT], mur[GMM_KP];
        #pragma unroll
        for (int j = 0; j < PPT; j++) { accA[j] = 0ULL; accB[j] = 0ULL; }
        #pragma unroll
        for (int k = 0; k < GMM_KP; k++) {
            const ull a = sA[m * GMM_KP + k];
            const ull b = sB[m * GMM_KP + k];
            mur[k] = sMu[m * GMM_KP + k];
            #pragma unroll
            for (int j = 0; j < PPT; j++) {
                accA[j] = fma2(a, xx[j][k], accA[j]);
                accB[j] = fma2(b, x[j][k],  accB[j]);
            }
        }
        const float c = sC[m];
        #pragma unroll
        for (int j = 0; j < PPT; j++) {
            float al, ah, bl, bh;
            upk2(accA[j], al, ah);
            upk2(accB[j], bl, bh);
            const float arg = c + ((al + ah) + (bl + bh));
            const float p   = __expf(arg);
            like[j] += p;
            const ull pb = pk2(p, p);
            #pragma unroll
            for (int k = 0; k < GMM_KP; k++)
                num[j][k] = fma2(pb, mur[k], num[j][k]);
        }
    }

    float ll = 0.0f;
    #pragma unroll
    for (int j = 0; j < PPT; j++) {
        if (v[j]) {
            const float inv = __fdividef(1.0f, like[j]);
            float* oe = out + 1 + (size_t)t[j] * GMM_D;
            #pragma unroll
            for (int k = 0; k < GMM_KP; k++) {
                float f0, f1;
                upk2(num[j][k], f0, f1);
                oe[2 * k]     = f0 * inv;
                oe[2 * k + 1] = f1 * inv;
            }
            ll += __logf(like[j]);
        }
    }

    // deterministic fixed-tree block reduction of log-likes
    sRed[tid] = ll;
    __syncthreads();
    #pragma unroll
    for (int s = TPB / 2; s > 0; s >>= 1) {
        if (tid < s) sRed[tid] += sRed[tid + s];
        __syncthreads();
    }
    if (tid == 0) g_part[blockIdx.x] = sRed[0];
}

// ---------- kernel 3: finalize log-like mean (deterministic tree) ----------
__global__ void gmm_finalize(float* __restrict__ out, int nblocks, float invT) {
    __shared__ float s[1024];
    const int tid = threadIdx.x;
    float acc = 0.0f;
    for (int i = tid; i < nblocks; i += 1024) acc += g_part[i];
    s[tid] = acc;
    __syncthreads();
    #pragma unroll
    for (int st = 512; st > 0; st >>= 1) {
        if (tid < st) s[tid] += s[tid + st];
        __syncthreads();
    }
    if (tid == 0) out[0] = s[0] * invT;
}

extern "C" void kernel_launch(void* const* d_in, const int* in_sizes, int n_in,
                              void* d_out, int out_size) {
    const float* data  = (const float*)d_in[0];
    const float* wghts = (const float*)d_in[1];
    const float* means = (const float*)d_in[2];
    const float* dcovs = (const float*)d_in[3];
    float* out = (float*)d_out;

    const int T = in_sizes[0] / GMM_D;
    const int nblocks = (T + PPB - 1) / PPB;

    gmm_precompute<<<1, GMM_M>>>(wghts, means, dcovs);
    gmm_main<<<nblocks, TPB>>>(data, means, out, T);
    gmm_finalize<<<1, 1024>>>(out, nblocks, 1.0f / (float)T);
}